// round 2
// baseline (speedup 1.0000x reference)
#include <cuda_runtime.h>
#include <cuda_bf16.h>

#define N_NODES 50000
#define E_EDGES 1600000
#define IN_F 512
#define HID 64
#define OUT_F 7

// ---------------- scratch (static device globals; no allocation) -------------
__device__ float g_dinv[N_NODES];
__device__ int   g_count[N_NODES];
__device__ int   g_rowstart[N_NODES + 1];
__device__ int   g_cursor[N_NODES];
__device__ int   g_srcs[E_EDGES];
__device__ float g_h1[(size_t)N_NODES * HID];   // x @ W1
__device__ float g_h2[(size_t)N_NODES * 8];     // relu(agg1+b1) @ W2, stride 8
__device__ int   g_is64;                        // edge_index dtype flag

// ---------------- edge_index dtype detection ---------------------------------
// If values are int64 in [0, 50000), every odd int32 word (hi half) is 0.
__global__ void detect_kernel(const int* __restrict__ ei32) {
    if (threadIdx.x == 0 && blockIdx.x == 0) {
        int all_zero = 1;
        for (int i = 0; i < 64; i++) {
            if (ei32[2 * i + 1] != 0) { all_zero = 0; break; }
        }
        g_is64 = all_zero;
    }
}

__device__ __forceinline__ int load_idx(const int* ei32, long long pos, int is64) {
    if (is64) {
        const long long* p = (const long long*)ei32;
        return (int)p[pos];
    }
    return ei32[pos];
}

// ---------------- degree / dinv ----------------------------------------------
__global__ void zero_count_kernel() {
    int i = blockIdx.x * blockDim.x + threadIdx.x;
    if (i < N_NODES) g_count[i] = 0;
}

__global__ void hist_kernel(const int* __restrict__ ei32, int E) {
    int e = blockIdx.x * blockDim.x + threadIdx.x;
    if (e < E) {
        int is64 = g_is64;
        unsigned dst = (unsigned)load_idx(ei32, (long long)E + e, is64);
        if (dst < N_NODES) atomicAdd(&g_count[dst], 1);
    }
}

__global__ void dinv_kernel() {
    int i = blockIdx.x * blockDim.x + threadIdx.x;
    if (i < N_NODES) {
        // degree includes the self loop -> always >= 1
        g_dinv[i] = rsqrtf((float)(g_count[i] + 1));
    }
}

// ---------------- exclusive scan over counts (single block) ------------------
__global__ void scan_kernel() {
    __shared__ int sums[1024];
    const int n = N_NODES;
    const int CH = (n + 1023) / 1024;       // 49
    int tid = threadIdx.x;
    int beg = tid * CH;
    int end = min(beg + CH, n);
    int s = 0;
    for (int i = beg; i < end; i++) s += g_count[i];
    sums[tid] = s;
    __syncthreads();
    // Hillis-Steele inclusive scan
    for (int off = 1; off < 1024; off <<= 1) {
        int v = (tid >= off) ? sums[tid - off] : 0;
        __syncthreads();
        sums[tid] += v;
        __syncthreads();
    }
    int run = (tid > 0) ? sums[tid - 1] : 0;
    for (int i = beg; i < end; i++) {
        g_rowstart[i] = run;
        g_cursor[i]   = run;
        run += g_count[i];
    }
    if (tid == 1023) g_rowstart[n] = run;
}

// ---------------- CSR fill (sort edges by dst) -------------------------------
__global__ void fill_kernel(const int* __restrict__ ei32, int E) {
    int e = blockIdx.x * blockDim.x + threadIdx.x;
    if (e < E) {
        int is64 = g_is64;
        unsigned src = (unsigned)load_idx(ei32, e, is64);
        unsigned dst = (unsigned)load_idx(ei32, (long long)E + e, is64);
        if (src < N_NODES && dst < N_NODES) {
            int pos = atomicAdd(&g_cursor[dst], 1);
            if (pos < E_EDGES) g_srcs[pos] = (int)src;
        }
    }
}

// ---------------- GEMM1: h1 = x @ W1  (50000x512 @ 512x64) -------------------
// Block tile 128x64, K-tile 16, 256 threads, per-thread 8x4 micro-tile.
__global__ __launch_bounds__(256) void gemm1_kernel(const float* __restrict__ x,
                                                    const float* __restrict__ W1) {
    __shared__ float As[16][128];   // transposed: As[k][m]
    __shared__ float Bs[16][64];

    int tid = threadIdx.x;
    int bm0 = blockIdx.x * 128;
    int tx = tid & 15;              // 0..15 -> 4 cols each
    int ty = tid >> 4;              // 0..15 -> 8 rows each

    float acc[8][4];
#pragma unroll
    for (int i = 0; i < 8; i++)
#pragma unroll
        for (int j = 0; j < 4; j++) acc[i][j] = 0.f;

    for (int k0 = 0; k0 < IN_F; k0 += 16) {
        // load A tile 128x16 (2 float4 per thread)
#pragma unroll
        for (int r = 0; r < 2; r++) {
            int idx = tid + r * 256;        // 0..511
            int row = idx >> 2;             // 0..127
            int k4  = idx & 3;              // 0..3
            float4 v = make_float4(0.f, 0.f, 0.f, 0.f);
            int gr = bm0 + row;
            if (gr < N_NODES)
                v = *(const float4*)(x + (size_t)gr * IN_F + k0 + k4 * 4);
            As[k4 * 4 + 0][row] = v.x;
            As[k4 * 4 + 1][row] = v.y;
            As[k4 * 4 + 2][row] = v.z;
            As[k4 * 4 + 3][row] = v.w;
        }
        // load B tile 16x64 (1 float4 per thread)
        {
            int k  = tid >> 4;              // 0..15
            int n4 = tid & 15;              // 0..15
            float4 v = *(const float4*)(W1 + (size_t)(k0 + k) * HID + n4 * 4);
            *(float4*)(&Bs[k][n4 * 4]) = v;
        }
        __syncthreads();

#pragma unroll
        for (int kk = 0; kk < 16; kk++) {
            float a[8], b[4];
#pragma unroll
            for (int i = 0; i < 8; i++) a[i] = As[kk][ty * 8 + i];
#pragma unroll
            for (int j = 0; j < 4; j++) b[j] = Bs[kk][tx * 4 + j];
#pragma unroll
            for (int i = 0; i < 8; i++)
#pragma unroll
                for (int j = 0; j < 4; j++) acc[i][j] = fmaf(a[i], b[j], acc[i][j]);
        }
        __syncthreads();
    }

#pragma unroll
    for (int i = 0; i < 8; i++) {
        int row = bm0 + ty * 8 + i;
        if (row < N_NODES) {
            float4 v = make_float4(acc[i][0], acc[i][1], acc[i][2], acc[i][3]);
            *(float4*)(g_h1 + (size_t)row * HID + tx * 4) = v;
        }
    }
}

// ---------------- gather1: agg1 -> relu(+b1) -> fused @W2 -> h2 --------------
// One warp per node. Lane holds features (lane, lane+32).
__global__ __launch_bounds__(256) void gather1_kernel(const float* __restrict__ W2,
                                                      const float* __restrict__ b1) {
    int node = (blockIdx.x * blockDim.x + threadIdx.x) >> 5;
    int lane = threadIdx.x & 31;
    if (node >= N_NODES) return;

    float di = g_dinv[node];
    float self_w = di * di;
    float v0 = g_h1[(size_t)node * HID + lane]      * self_w;
    float v1 = g_h1[(size_t)node * HID + 32 + lane] * self_w;

    int beg = g_rowstart[node];
    int end = g_rowstart[node + 1];
    for (int e = beg; e < end; e += 32) {
        int s = 0; float w = 0.f;
        if (e + lane < end) {
            s = g_srcs[e + lane];
            w = g_dinv[s] * di;
        }
        int cnt = min(32, end - e);
        for (int j = 0; j < cnt; j++) {
            int   ss = __shfl_sync(0xffffffffu, s, j);
            float ww = __shfl_sync(0xffffffffu, w, j);
            v0 = fmaf(g_h1[(size_t)ss * HID + lane],      ww, v0);
            v1 = fmaf(g_h1[(size_t)ss * HID + 32 + lane], ww, v1);
        }
    }

    v0 = fmaxf(v0 + b1[lane],      0.f);
    v1 = fmaxf(v1 + b1[lane + 32], 0.f);

    // fused GEMM2: h2[node][o] = sum_c relu_row[c] * W2[c][o]
    float acc[OUT_F];
#pragma unroll
    for (int o = 0; o < OUT_F; o++)
        acc[o] = v0 * __ldg(&W2[lane * OUT_F + o]) +
                 v1 * __ldg(&W2[(lane + 32) * OUT_F + o]);
#pragma unroll
    for (int off = 16; off; off >>= 1)
#pragma unroll
        for (int o = 0; o < OUT_F; o++)
            acc[o] += __shfl_xor_sync(0xffffffffu, acc[o], off);

    if (lane == 0) {
#pragma unroll
        for (int o = 0; o < OUT_F; o++) g_h2[(size_t)node * 8 + o] = acc[o];
    }
}

// ---------------- gather2: out = agg2(h2) + b2 -------------------------------
// One warp per node: 4 groups of 8 lanes; lane%8 = feature, lane/8 = edge group.
__global__ __launch_bounds__(256) void gather2_kernel(const float* __restrict__ b2,
                                                      float* __restrict__ out) {
    int node = (blockIdx.x * blockDim.x + threadIdx.x) >> 5;
    int lane = threadIdx.x & 31;
    if (node >= N_NODES) return;

    int o = lane & 7;
    int g = lane >> 3;
    float di = g_dinv[node];

    float acc = 0.f;
    if (g == 0 && o < OUT_F) acc = di * di * g_h2[(size_t)node * 8 + o];

    int beg = g_rowstart[node];
    int end = g_rowstart[node + 1];
    for (int e = beg + g; e < end; e += 4) {
        int s = g_srcs[e];
        float w = g_dinv[s] * di;
        if (o < OUT_F) acc = fmaf(w, g_h2[(size_t)s * 8 + o], acc);
    }
    acc += __shfl_xor_sync(0xffffffffu, acc, 8);
    acc += __shfl_xor_sync(0xffffffffu, acc, 16);

    if (lane < OUT_F) out[(size_t)node * OUT_F + lane] = acc + b2[lane];
}

// ---------------- launch -----------------------------------------------------
extern "C" void kernel_launch(void* const* d_in, const int* in_sizes, int n_in,
                              void* d_out, int out_size) {
    // Identify inputs by element count (robust to metadata ordering).
    const float* x  = nullptr;
    const int*   ei = nullptr;   // raw words; dtype detected on device
    const float* W1 = nullptr;
    const float* b1 = nullptr;
    const float* W2 = nullptr;
    const float* b2 = nullptr;
    long long ei_elems = 0;

    for (int i = 0; i < n_in; i++) {
        long long sz = in_sizes[i];
        if      (sz == (long long)N_NODES * IN_F) x  = (const float*)d_in[i];
        else if (sz == (long long)IN_F * HID)     W1 = (const float*)d_in[i];
        else if (sz == HID)                       b1 = (const float*)d_in[i];
        else if (sz == HID * OUT_F)               W2 = (const float*)d_in[i];
        else if (sz == OUT_F)                     b2 = (const float*)d_in[i];
        else { ei = (const int*)d_in[i]; ei_elems = sz; }
    }

    int E = (int)(ei_elems / 2);
    if (E > E_EDGES) E = E_EDGES;
    float* out = (float*)d_out;

    detect_kernel<<<1, 32>>>(ei);
    zero_count_kernel<<<(N_NODES + 255) / 256, 256>>>();
    hist_kernel<<<(E + 255) / 256, 256>>>(ei, E);
    dinv_kernel<<<(N_NODES + 255) / 256, 256>>>();
    scan_kernel<<<1, 1024>>>();
    fill_kernel<<<(E + 255) / 256, 256>>>(ei, E);

    gemm1_kernel<<<(N_NODES + 127) / 128, 256>>>(x, W1);
    gather1_kernel<<<(N_NODES + 7) / 8, 256>>>(W2, b1);
    gather2_kernel<<<(N_NODES + 7) / 8, 256>>>(b2, out);
}

// round 4
// speedup vs baseline: 1.0701x; 1.0701x over previous
#include <cuda_runtime.h>
#include <cuda_bf16.h>
#include <cstdint>

#define N_NODES 50000
#define E_EDGES 1600000
#define IN_F 512
#define HID 64
#define OUT_F 7
#define MTILES 3125              // 50000 / 16
#define KSTEPS 32                // 512 / 16
#define NTILES 8                 // 64 / 8

// ---------------- scratch (static device globals; no allocation) -------------
__device__ float g_dinv[N_NODES];
__device__ int   g_count[N_NODES];
__device__ int   g_rowstart[N_NODES + 1];
__device__ int   g_cursor[N_NODES];
__device__ int   g_srcs[E_EDGES];
__device__ float g_h1[(size_t)N_NODES * HID];    // x @ W1
__device__ float g_h2[(size_t)N_NODES * 8];      // relu(agg1+b1) @ W2, stride 8
__device__ int   g_is64;                         // edge_index dtype flag
// Pre-packed W1 B-fragments in mma register layout: [ntile][kstep][lane]
__device__ uint2 g_bfragH[NTILES * KSTEPS * 32];
__device__ uint2 g_bfragL[NTILES * KSTEPS * 32];

// ---------------- helpers ----------------------------------------------------
__device__ __forceinline__ void mma16816(float* d, const uint32_t* a, const uint32_t b0,
                                         const uint32_t b1) {
    asm volatile(
        "mma.sync.aligned.m16n8k16.row.col.f32.bf16.bf16.f32 "
        "{%0,%1,%2,%3}, {%4,%5,%6,%7}, {%8,%9}, {%0,%1,%2,%3};"
        : "+f"(d[0]), "+f"(d[1]), "+f"(d[2]), "+f"(d[3])
        : "r"(a[0]), "r"(a[1]), "r"(a[2]), "r"(a[3]), "r"(b0), "r"(b1));
}

// fp32 pair -> packed bf16x2 hi + packed bf16x2 lo (split precision)
__device__ __forceinline__ void cvt_pair(float fa, float fb, uint32_t& hi, uint32_t& lo) {
    __nv_bfloat16 ha = __float2bfloat16_rn(fa);
    __nv_bfloat16 hb = __float2bfloat16_rn(fb);
    __nv_bfloat16 la = __float2bfloat16_rn(fa - __bfloat162float(ha));
    __nv_bfloat16 lb = __float2bfloat16_rn(fb - __bfloat162float(hb));
    hi = ((uint32_t)__bfloat16_as_ushort(hb) << 16) | (uint32_t)__bfloat16_as_ushort(ha);
    lo = ((uint32_t)__bfloat16_as_ushort(lb) << 16) | (uint32_t)__bfloat16_as_ushort(la);
}

// ---------------- W1 fragment pre-pack ---------------------------------------
// b0 covers k = k0+tg*2, k0+tg*2+1 ; b1 covers +8. n = nt*8 + (lane>>2).
__global__ void w1frag_kernel(const float* __restrict__ W1) {
    int idx = blockIdx.x * blockDim.x + threadIdx.x;
    if (idx >= NTILES * KSTEPS * 32) return;
    int lane = idx & 31;
    int ks   = (idx >> 5) & 31;
    int nt   = idx >> 10;
    int tg = lane & 3, gp = lane >> 2;
    int n  = nt * 8 + gp;
    int k  = ks * 16 + tg * 2;
    float f00 = W1[(size_t)(k)     * HID + n];
    float f01 = W1[(size_t)(k + 1) * HID + n];
    float f10 = W1[(size_t)(k + 8) * HID + n];
    float f11 = W1[(size_t)(k + 9) * HID + n];
    uint32_t h0, l0, h1, l1;
    cvt_pair(f00, f01, h0, l0);
    cvt_pair(f10, f11, h1, l1);
    g_bfragH[idx] = make_uint2(h0, h1);
    g_bfragL[idx] = make_uint2(l0, l1);
}

// ---------------- edge_index dtype detection ---------------------------------
__global__ void detect_kernel(const int* __restrict__ ei32) {
    if (threadIdx.x == 0 && blockIdx.x == 0) {
        int all_zero = 1;
        for (int i = 0; i < 64; i++) {
            if (ei32[2 * i + 1] != 0) { all_zero = 0; break; }
        }
        g_is64 = all_zero;
    }
}

__device__ __forceinline__ int load_idx(const int* ei32, long long pos, int is64) {
    if (is64) {
        const long long* p = (const long long*)ei32;
        return (int)p[pos];
    }
    return ei32[pos];
}

// ---------------- degree histogram -------------------------------------------
__global__ void zero_count_kernel() {
    int i = blockIdx.x * blockDim.x + threadIdx.x;
    if (i < N_NODES) g_count[i] = 0;
}

__global__ void hist_kernel(const int* __restrict__ ei32, int E) {
    int e = blockIdx.x * blockDim.x + threadIdx.x;
    if (e < E) {
        int is64 = g_is64;
        unsigned dst = (unsigned)load_idx(ei32, (long long)E + e, is64);
        if (dst < N_NODES) atomicAdd(&g_count[dst], 1);
    }
}

// ---------------- exclusive scan + dinv (single block) -----------------------
__global__ void scan_kernel() {
    __shared__ int sums[1024];
    const int n = N_NODES;
    const int CH = (n + 1023) / 1024;
    int tid = threadIdx.x;
    int beg = tid * CH;
    int end = min(beg + CH, n);
    int s = 0;
    for (int i = beg; i < end; i++) s += g_count[i];
    sums[tid] = s;
    __syncthreads();
    for (int off = 1; off < 1024; off <<= 1) {
        int v = (tid >= off) ? sums[tid - off] : 0;
        __syncthreads();
        sums[tid] += v;
        __syncthreads();
    }
    int run = (tid > 0) ? sums[tid - 1] : 0;
    for (int i = beg; i < end; i++) {
        int c = g_count[i];
        g_rowstart[i] = run;
        g_cursor[i]   = run;
        g_dinv[i]     = rsqrtf((float)(c + 1));   // deg includes self-loop
        run += c;
    }
    if (tid == 1023) g_rowstart[n] = run;
}

// ---------------- CSR fill (sort edges by dst) -------------------------------
__global__ void fill_kernel(const int* __restrict__ ei32, int E) {
    int e = blockIdx.x * blockDim.x + threadIdx.x;
    if (e < E) {
        int is64 = g_is64;
        unsigned src = (unsigned)load_idx(ei32, e, is64);
        unsigned dst = (unsigned)load_idx(ei32, (long long)E + e, is64);
        if (src < N_NODES && dst < N_NODES) {
            int pos = atomicAdd(&g_cursor[dst], 1);
            if (pos < E_EDGES) g_srcs[pos] = (int)src;
        }
    }
}

// ---------------- GEMM1 via mma.sync bf16 split precision --------------------
// One warp computes a 16x64 tile of h1 = x @ W1.
// D = xh*wh + xh*wl + xl*wh, fp32 accumulate (err ~2^-18).
__global__ __launch_bounds__(256) void gemm1_mma_kernel(const float* __restrict__ x) {
    int wg   = (blockIdx.x * blockDim.x + threadIdx.x) >> 5;
    int lane = threadIdx.x & 31;
    if (wg >= MTILES) return;

    int gp = lane >> 2, tg = lane & 3;
    int row0 = wg * 16;

    const float* xr0 = x + (size_t)(row0 + gp)     * IN_F + tg * 2;
    const float* xr1 = x + (size_t)(row0 + gp + 8) * IN_F + tg * 2;

    float acc[NTILES][4];
#pragma unroll
    for (int nt = 0; nt < NTILES; nt++)
#pragma unroll
        for (int j = 0; j < 4; j++) acc[nt][j] = 0.f;

    for (int ks = 0; ks < KSTEPS; ks++) {
        int k0 = ks * 16;
        float2 f0 = *(const float2*)(xr0 + k0);       // a0: (gp,   k0+tg*2)
        float2 f1 = *(const float2*)(xr1 + k0);       // a1: (gp+8, k0+tg*2)
        float2 f2 = *(const float2*)(xr0 + k0 + 8);   // a2: (gp,   k0+8+tg*2)
        float2 f3 = *(const float2*)(xr1 + k0 + 8);   // a3: (gp+8, k0+8+tg*2)

        uint32_t ah[4], al[4];
        cvt_pair(f0.x, f0.y, ah[0], al[0]);
        cvt_pair(f1.x, f1.y, ah[1], al[1]);
        cvt_pair(f2.x, f2.y, ah[2], al[2]);
        cvt_pair(f3.x, f3.y, ah[3], al[3]);

#pragma unroll
        for (int nt = 0; nt < NTILES; nt++) {
            uint2 bh = g_bfragH[(nt * KSTEPS + ks) * 32 + lane];
            uint2 bl = g_bfragL[(nt * KSTEPS + ks) * 32 + lane];
            mma16816(acc[nt], ah, bh.x, bh.y);
            mma16816(acc[nt], ah, bl.x, bl.y);
            mma16816(acc[nt], al, bh.x, bh.y);
        }
    }

    int r0 = row0 + gp, r1 = r0 + 8;
#pragma unroll
    for (int nt = 0; nt < NTILES; nt++) {
        int c = nt * 8 + tg * 2;
        *(float2*)(g_h1 + (size_t)r0 * HID + c) = make_float2(acc[nt][0], acc[nt][1]);
        *(float2*)(g_h1 + (size_t)r1 * HID + c) = make_float2(acc[nt][2], acc[nt][3]);
    }
}

// ---------------- gather1: agg1 -> relu(+b1) -> fused @W2 -> h2 --------------
__global__ __launch_bounds__(256) void gather1_kernel(const float* __restrict__ W2,
                                                      const float* __restrict__ b1) {
    int node = (blockIdx.x * blockDim.x + threadIdx.x) >> 5;
    int lane = threadIdx.x & 31;
    if (node >= N_NODES) return;

    float di = g_dinv[node];
    float self_w = di * di;
    float v0 = g_h1[(size_t)node * HID + lane]      * self_w;
    float v1 = g_h1[(size_t)node * HID + 32 + lane] * self_w;

    int beg = g_rowstart[node];
    int end = g_rowstart[node + 1];
    for (int e = beg; e < end; e += 32) {
        int s = 0; float w = 0.f;
        if (e + lane < end) {
            s = g_srcs[e + lane];
            w = g_dinv[s] * di;
        }
        int cnt = min(32, end - e);
        for (int j = 0; j < cnt; j++) {
            int   ss = __shfl_sync(0xffffffffu, s, j);
            float ww = __shfl_sync(0xffffffffu, w, j);
            v0 = fmaf(g_h1[(size_t)ss * HID + lane],      ww, v0);
            v1 = fmaf(g_h1[(size_t)ss * HID + 32 + lane], ww, v1);
        }
    }

    v0 = fmaxf(v0 + b1[lane],      0.f);
    v1 = fmaxf(v1 + b1[lane + 32], 0.f);

    float acc[OUT_F];
#pragma unroll
    for (int o = 0; o < OUT_F; o++)
        acc[o] = v0 * __ldg(&W2[lane * OUT_F + o]) +
                 v1 * __ldg(&W2[(lane + 32) * OUT_F + o]);
#pragma unroll
    for (int off = 16; off; off >>= 1)
#pragma unroll
        for (int o = 0; o < OUT_F; o++)
            acc[o] += __shfl_xor_sync(0xffffffffu, acc[o], off);

    if (lane == 0) {
#pragma unroll
        for (int o = 0; o < OUT_F; o++) g_h2[(size_t)node * 8 + o] = acc[o];
    }
}

// ---------------- gather2: out = agg2(h2) + b2 -------------------------------
__global__ __launch_bounds__(256) void gather2_kernel(const float* __restrict__ b2,
                                                      float* __restrict__ out) {
    int node = (blockIdx.x * blockDim.x + threadIdx.x) >> 5;
    int lane = threadIdx.x & 31;
    if (node >= N_NODES) return;

    int o = lane & 7;
    int g = lane >> 3;
    float di = g_dinv[node];

    float acc = 0.f;
    if (g == 0 && o < OUT_F) acc = di * di * g_h2[(size_t)node * 8 + o];

    int beg = g_rowstart[node];
    int end = g_rowstart[node + 1];
    for (int e = beg + g; e < end; e += 4) {
        int s = g_srcs[e];
        float w = g_dinv[s] * di;
        if (o < OUT_F) acc = fmaf(w, g_h2[(size_t)s * 8 + o], acc);
    }
    acc += __shfl_xor_sync(0xffffffffu, acc, 8);
    acc += __shfl_xor_sync(0xffffffffu, acc, 16);

    if (lane < OUT_F) out[(size_t)node * OUT_F + lane] = acc + b2[lane];
}

// ---------------- launch -----------------------------------------------------
extern "C" void kernel_launch(void* const* d_in, const int* in_sizes, int n_in,
                              void* d_out, int out_size) {
    const float* x  = nullptr;
    const int*   ei = nullptr;
    const float* W1 = nullptr;
    const float* b1 = nullptr;
    const float* W2 = nullptr;
    const float* b2 = nullptr;
    long long ei_elems = 0;

    for (int i = 0; i < n_in; i++) {
        long long sz = in_sizes[i];
        if      (sz == (long long)N_NODES * IN_F) x  = (const float*)d_in[i];
        else if (sz == (long long)IN_F * HID)     W1 = (const float*)d_in[i];
        else if (sz == HID)                       b1 = (const float*)d_in[i];
        else if (sz == HID * OUT_F)               W2 = (const float*)d_in[i];
        else if (sz == OUT_F)                     b2 = (const float*)d_in[i];
        else { ei = (const int*)d_in[i]; ei_elems = sz; }
    }

    int E = (int)(ei_elems / 2);
    if (E > E_EDGES) E = E_EDGES;
    float* out = (float*)d_out;

    // Launch order places gemm1_mma at index 5 for the ncu -s 5 -c 1 window.
    w1frag_kernel<<<(NTILES * KSTEPS * 32 + 255) / 256, 256>>>(W1);        // 0
    detect_kernel<<<1, 32>>>(ei);                                          // 1
    zero_count_kernel<<<(N_NODES + 255) / 256, 256>>>();                   // 2
    hist_kernel<<<(E + 255) / 256, 256>>>(ei, E);                          // 3
    scan_kernel<<<1, 1024>>>();                                            // 4
    gemm1_mma_kernel<<<(MTILES * 32 + 255) / 256, 256>>>(x);               // 5
    fill_kernel<<<(E + 255) / 256, 256>>>(ei, E);                          // 6
    gather1_kernel<<<(N_NODES + 7) / 8, 256>>>(W2, b1);                    // 7
    gather2_kernel<<<(N_NODES + 7) / 8, 256>>>(b2, out);                   // 8
}